// round 1
// baseline (speedup 1.0000x reference)
#include <cuda_runtime.h>

#define BB 4
#define TT 8
#define CC 64
#define FF 16
#define NN 8192   // T*H*W
#define HW 1024

// Scratch (no allocations allowed): pooled transposed as float4 over batch,
// sigmoid output v, and a work-stealing counter for the persistent GEMV grid.
__device__ float4 g_p4[NN];        // g_p4[n] = (pooled[b=0..3][n])
__device__ float  g_v[BB * NN];    // v[b*N + n]
__device__ int    g_ctr;

// ---------------------------------------------------------------------------
// Kernel 1: pooled[b,n] = sum_c mean_f(conv1_w[f,c]) * x[b,t,c,hw] + mean_f(b)
// One thread per (b,n). Coalesced over hw for every c. Also resets g_ctr.
// ---------------------------------------------------------------------------
__global__ __launch_bounds__(256) void k_pool(const float* __restrict__ x,
                                              const float* __restrict__ c1w,
                                              const float* __restrict__ c1b) {
    __shared__ float swb[CC];
    __shared__ float sbb;
    int tid = threadIdx.x;
    if (tid < CC) {
        float s = 0.f;
        #pragma unroll
        for (int f = 0; f < FF; f++) s += c1w[f * CC + tid];
        swb[tid] = s * (1.0f / FF);
    }
    if (tid == 0) {
        float s = 0.f;
        #pragma unroll
        for (int f = 0; f < FF; f++) s += c1b[f];
        sbb = s * (1.0f / FF);
        if (blockIdx.x == 0) g_ctr = 0;   // reset work counter for k_gemv
    }
    __syncthreads();

    int g  = blockIdx.x * 256 + tid;      // 0..32767
    int b  = g >> 13;
    int n  = g & (NN - 1);
    int t  = n >> 10;
    int hw = n & (HW - 1);
    const float* xp = x + (size_t)((b * TT + t) * CC) * HW + hw;

    float a0 = sbb, a1 = 0.f;
    #pragma unroll 8
    for (int c = 0; c < CC; c += 2) {
        a0 += swb[c]     * xp[c * HW];
        a1 += swb[c + 1] * xp[(c + 1) * HW];
    }
    ((float*)g_p4)[n * 4 + b] = a0 + a1;
}

// ---------------------------------------------------------------------------
// Kernel 2: v[b,n] = sigmoid( sum_m pooled[b,m] * W[n,m] + bias[n] )
// Persistent blocks (1 CTA/SM, 128KB smem). Pooled held in SMEM as 4
// de-interleaved float4 planes (conflict-free LDS.128). Each warp grabs a
// 4-row task via atomic counter; 4 rows x 4 batches = 16 accumulators so the
// SMEM:DRAM byte ratio is 1:1. DRAM-bound: streams the 256MB weight matrix.
// ---------------------------------------------------------------------------
__global__ __launch_bounds__(256) void k_gemv(const float* __restrict__ Wm,
                                              const float* __restrict__ bias) {
    extern __shared__ float4 sp[];   // sp[j*2048 + i] = g_p4[4*i + j], 128KB
    for (int idx = threadIdx.x; idx < NN; idx += 256)
        sp[(idx & 3) * 2048 + (idx >> 2)] = g_p4[idx];
    __syncthreads();

    int lane = threadIdx.x & 31;
    const float4* W4 = (const float4*)Wm;   // row stride = N/4 = 2048 float4

    for (;;) {
        int task;
        if (lane == 0) task = atomicAdd(&g_ctr, 1);
        task = __shfl_sync(0xffffffffu, task, 0);
        if (task >= NN / 4) break;
        int n0 = task * 4;
        const float4* w0 = W4 + (size_t)n0 * (NN / 4);

        float acc[4][4];
        #pragma unroll
        for (int r = 0; r < 4; r++)
            #pragma unroll
            for (int b = 0; b < 4; b++) acc[r][b] = 0.f;

        #pragma unroll 2
        for (int i = lane; i < NN / 4; i += 32) {
            float4 wv0 = w0[i];
            float4 wv1 = w0[2048 + i];
            float4 wv2 = w0[4096 + i];
            float4 wv3 = w0[6144 + i];
            float4 p0 = sp[i];
            float4 p1 = sp[2048 + i];
            float4 p2 = sp[4096 + i];
            float4 p3 = sp[6144 + i];
            float4 wv[4] = {wv0, wv1, wv2, wv3};
            #pragma unroll
            for (int r = 0; r < 4; r++) {
                acc[r][0] += wv[r].x * p0.x + wv[r].y * p1.x + wv[r].z * p2.x + wv[r].w * p3.x;
                acc[r][1] += wv[r].x * p0.y + wv[r].y * p1.y + wv[r].z * p2.y + wv[r].w * p3.y;
                acc[r][2] += wv[r].x * p0.z + wv[r].y * p1.z + wv[r].z * p2.z + wv[r].w * p3.z;
                acc[r][3] += wv[r].x * p0.w + wv[r].y * p1.w + wv[r].z * p2.w + wv[r].w * p3.w;
            }
        }

        #pragma unroll
        for (int r = 0; r < 4; r++)
            #pragma unroll
            for (int b = 0; b < 4; b++)
                #pragma unroll
                for (int off = 16; off > 0; off >>= 1)
                    acc[r][b] += __shfl_xor_sync(0xffffffffu, acc[r][b], off);

        if (lane < 16) {
            int r = lane >> 2, b = lane & 3;
            float z = acc[r][b] + bias[n0 + r];
            g_v[b * NN + n0 + r] = 1.0f / (1.0f + __expf(-z));
        }
    }
}

// ---------------------------------------------------------------------------
// Kernel 3: out[b,t,f,h,w] = v[b,n] * (sum_c g3_w[f,c]*x[b,t,c,hw] + g3_b[f])
// One thread per (b,t,hw), 16 f-accumulators in registers, weights in SMEM.
// ---------------------------------------------------------------------------
__global__ __launch_bounds__(256) void k_out(const float* __restrict__ x,
                                             const float* __restrict__ g3w,
                                             const float* __restrict__ g3b,
                                             float* __restrict__ out) {
    __shared__ float sw[FF * CC];
    __shared__ float sb[FF];
    for (int idx = threadIdx.x; idx < FF * CC; idx += 256) sw[idx] = g3w[idx];
    if (threadIdx.x < FF) sb[threadIdx.x] = g3b[threadIdx.x];
    __syncthreads();

    int g  = blockIdx.x * 256 + threadIdx.x;
    int b  = g >> 13;
    int n  = g & (NN - 1);
    int t  = n >> 10;
    int hw = n & (HW - 1);
    const float* xp = x + (size_t)((b * TT + t) * CC) * HW + hw;

    float acc[FF];
    #pragma unroll
    for (int f = 0; f < FF; f++) acc[f] = sb[f];

    #pragma unroll 4
    for (int c = 0; c < CC; c++) {
        float xv = xp[c * HW];
        #pragma unroll
        for (int f = 0; f < FF; f++) acc[f] += sw[f * CC + c] * xv;
    }

    float v = g_v[b * NN + n];
    float* op = out + (size_t)((b * TT + t) * FF) * HW + hw;
    #pragma unroll
    for (int f = 0; f < FF; f++) op[f * HW] = v * acc[f];
}

extern "C" void kernel_launch(void* const* d_in, const int* in_sizes, int n_in,
                              void* d_out, int out_size) {
    const float* x   = (const float*)d_in[0];
    // d_in[1] = x1, unused by the reference forward
    const float* c1w = (const float*)d_in[2];
    const float* c1b = (const float*)d_in[3];
    const float* g3w = (const float*)d_in[4];
    const float* g3b = (const float*)d_in[5];
    const float* fw  = (const float*)d_in[6];
    const float* fb  = (const float*)d_in[7];
    float* out = (float*)d_out;

    int nsm = 148;
    cudaDeviceGetAttribute(&nsm, cudaDevAttrMultiProcessorCount, 0);

    cudaFuncSetAttribute(k_gemv, cudaFuncAttributeMaxDynamicSharedMemorySize, 131072);

    k_pool<<<(BB * NN) / 256, 256>>>(x, c1w, c1b);
    k_gemv<<<nsm, 256, 131072>>>(fw, fb);
    k_out<<<(BB * NN) / 256, 256>>>(x, g3w, g3b, out);
}

// round 3
// speedup vs baseline: 1.8006x; 1.8006x over previous
#include <cuda_runtime.h>

#define BB 4
#define TT 8
#define CC 64
#define FF 16
#define NN 8192   // T*H*W
#define HW 1024

// Scratch: pooled transposed as float4 over batch, and sigmoid output v.
__device__ float4 g_p4[NN];        // g_p4[n] = (pooled[b=0..3][n])
__device__ float  g_v[BB * NN];    // v[b*N + n]

// ---------------------------------------------------------------------------
// Kernel 1: pooled[b,n] = sum_c mean_f(conv1_w[f,c]) * x[b,t,c,hw] + mean_f(b)
// 512 blocks x 128 threads. Each block: 64 outputs, 2 threads per output
// (c split in halves), smem combine. Coalesced 128B warp loads over hw.
// ---------------------------------------------------------------------------
__global__ __launch_bounds__(128) void k_pool(const float* __restrict__ x,
                                              const float* __restrict__ c1w,
                                              const float* __restrict__ c1b) {
    __shared__ float swb[CC];
    __shared__ float sbb;
    __shared__ float red[128];
    int tid = threadIdx.x;
    if (tid < CC) {
        float s = 0.f;
        #pragma unroll
        for (int f = 0; f < FF; f++) s += c1w[f * CC + tid];
        swb[tid] = s * (1.0f / FF);
    }
    if (tid == 0) {
        float s = 0.f;
        #pragma unroll
        for (int f = 0; f < FF; f++) s += c1b[f];
        sbb = s * (1.0f / FF);
    }
    __syncthreads();

    int o    = tid & 63;          // output within block
    int half = tid >> 6;          // c-half 0/1
    int g    = blockIdx.x * 64 + o;  // 0..32767
    int b    = g >> 13;
    int n    = g & (NN - 1);
    int t    = n >> 10;
    int hw   = n & (HW - 1);
    const float* xp = x + (size_t)((b * TT + t) * CC + half * 32) * HW + hw;

    float a0 = 0.f, a1 = 0.f;
    #pragma unroll
    for (int c = 0; c < 32; c += 2) {
        a0 += swb[half * 32 + c]     * xp[c * HW];
        a1 += swb[half * 32 + c + 1] * xp[(c + 1) * HW];
    }
    red[tid] = a0 + a1;
    __syncthreads();
    if (tid < 64) {
        float s = red[tid] + red[tid + 64] + sbb;
        ((float*)g_p4)[n * 4 + b] = s;
    }
}

// ---------------------------------------------------------------------------
// Kernel 2: v[b,n] = sigmoid( sum_m pooled[b,m] * W[n,m] + bias[n] )
// grid = #SMs, 512 threads (16 warps), 128KB smem (pooled, 4 deinterleaved
// float4 planes, conflict-free LDS.128). Static mapping: global warp w
// handles rows 4w..4w+3 for all 4 batches (16 scalar accumulators).
// 8 independent streaming LDG.128 per loop trip per warp.
// ---------------------------------------------------------------------------
__global__ __launch_bounds__(512) void k_gemv(const float* __restrict__ Wm,
                                              const float* __restrict__ bias) {
    extern __shared__ float4 sp[];   // sp[j*2048 + i] = g_p4[4*i + j], 128KB
    for (int idx = threadIdx.x; idx < NN; idx += 512)
        sp[(idx & 3) * 2048 + (idx >> 2)] = g_p4[idx];
    __syncthreads();

    int lane = threadIdx.x & 31;
    int gw   = blockIdx.x * 16 + (threadIdx.x >> 5);
    if (gw >= NN / 4) return;
    int n0 = gw * 4;
    const float4* w0 = (const float4*)Wm + (size_t)n0 * (NN / 4);

    float a00 = 0.f, a01 = 0.f, a02 = 0.f, a03 = 0.f;
    float a10 = 0.f, a11 = 0.f, a12 = 0.f, a13 = 0.f;
    float a20 = 0.f, a21 = 0.f, a22 = 0.f, a23 = 0.f;
    float a30 = 0.f, a31 = 0.f, a32 = 0.f, a33 = 0.f;

#define GEMV_BODY(I)                                                          \
    {                                                                         \
        float4 w0v = __ldcs(w0 + (I));                                        \
        float4 w1v = __ldcs(w0 + 2048 + (I));                                 \
        float4 w2v = __ldcs(w0 + 4096 + (I));                                 \
        float4 w3v = __ldcs(w0 + 6144 + (I));                                 \
        float4 p0 = sp[(I)];                                                  \
        float4 p1 = sp[2048 + (I)];                                           \
        float4 p2 = sp[4096 + (I)];                                           \
        float4 p3 = sp[6144 + (I)];                                           \
        a00 += w0v.x * p0.x + w0v.y * p1.x + w0v.z * p2.x + w0v.w * p3.x;     \
        a01 += w0v.x * p0.y + w0v.y * p1.y + w0v.z * p2.y + w0v.w * p3.y;     \
        a02 += w0v.x * p0.z + w0v.y * p1.z + w0v.z * p2.z + w0v.w * p3.z;     \
        a03 += w0v.x * p0.w + w0v.y * p1.w + w0v.z * p2.w + w0v.w * p3.w;     \
        a10 += w1v.x * p0.x + w1v.y * p1.x + w1v.z * p2.x + w1v.w * p3.x;     \
        a11 += w1v.x * p0.y + w1v.y * p1.y + w1v.z * p2.y + w1v.w * p3.y;     \
        a12 += w1v.x * p0.z + w1v.y * p1.z + w1v.z * p2.z + w1v.w * p3.z;     \
        a13 += w1v.x * p0.w + w1v.y * p1.w + w1v.z * p2.w + w1v.w * p3.w;     \
        a20 += w2v.x * p0.x + w2v.y * p1.x + w2v.z * p2.x + w2v.w * p3.x;     \
        a21 += w2v.x * p0.y + w2v.y * p1.y + w2v.z * p2.y + w2v.w * p3.y;     \
        a22 += w2v.x * p0.z + w2v.y * p1.z + w2v.z * p2.z + w2v.w * p3.z;     \
        a23 += w2v.x * p0.w + w2v.y * p1.w + w2v.z * p2.w + w2v.w * p3.w;     \
        a30 += w3v.x * p0.x + w3v.y * p1.x + w3v.z * p2.x + w3v.w * p3.x;     \
        a31 += w3v.x * p0.y + w3v.y * p1.y + w3v.z * p2.y + w3v.w * p3.y;     \
        a32 += w3v.x * p0.z + w3v.y * p1.z + w3v.z * p2.z + w3v.w * p3.z;     \
        a33 += w3v.x * p0.w + w3v.y * p1.w + w3v.z * p2.w + w3v.w * p3.w;     \
    }

    for (int i = lane; i < NN / 4; i += 64) {
        GEMV_BODY(i);
        GEMV_BODY(i + 32);
    }
#undef GEMV_BODY

    float acc[16] = {a00, a01, a02, a03, a10, a11, a12, a13,
                     a20, a21, a22, a23, a30, a31, a32, a33};
    #pragma unroll
    for (int k = 0; k < 16; k++)
        #pragma unroll
        for (int off = 16; off > 0; off >>= 1)
            acc[k] += __shfl_xor_sync(0xffffffffu, acc[k], off);

    if (lane < 16) {
        int r = lane >> 2, b = lane & 3;
        float z = acc[lane] + bias[n0 + r];
        g_v[b * NN + n0 + r] = 1.0f / (1.0f + __expf(-z));
    }
}

// ---------------------------------------------------------------------------
// Kernel 3: out[b,t,f,h,w] = v[b,n] * (sum_c g3_w[f,c]*x[b,t,c,hw] + g3_b[f])
// 256 blocks x 128 threads (grid > #SM), 16 f-accumulators, weights in SMEM.
// ---------------------------------------------------------------------------
__global__ __launch_bounds__(128) void k_out(const float* __restrict__ x,
                                             const float* __restrict__ g3w,
                                             const float* __restrict__ g3b,
                                             float* __restrict__ out) {
    __shared__ float sw[FF * CC];
    __shared__ float sb[FF];
    for (int idx = threadIdx.x; idx < FF * CC; idx += 128) sw[idx] = g3w[idx];
    if (threadIdx.x < FF) sb[threadIdx.x] = g3b[threadIdx.x];
    __syncthreads();

    int g  = blockIdx.x * 128 + threadIdx.x;
    int b  = g >> 13;
    int n  = g & (NN - 1);
    int t  = n >> 10;
    int hw = n & (HW - 1);
    const float* xp = x + (size_t)((b * TT + t) * CC) * HW + hw;

    float acc[FF];
    #pragma unroll
    for (int f = 0; f < FF; f++) acc[f] = sb[f];

    #pragma unroll 8
    for (int c = 0; c < CC; c++) {
        float xv = xp[c * HW];
        #pragma unroll
        for (int f = 0; f < FF; f++) acc[f] += sw[f * CC + c] * xv;
    }

    float v = g_v[b * NN + n];
    float* op = out + (size_t)((b * TT + t) * FF) * HW + hw;
    #pragma unroll
    for (int f = 0; f < FF; f++) op[f * HW] = v * acc[f];
}

extern "C" void kernel_launch(void* const* d_in, const int* in_sizes, int n_in,
                              void* d_out, int out_size) {
    const float* x   = (const float*)d_in[0];
    // d_in[1] = x1, unused by the reference forward
    const float* c1w = (const float*)d_in[2];
    const float* c1b = (const float*)d_in[3];
    const float* g3w = (const float*)d_in[4];
    const float* g3b = (const float*)d_in[5];
    const float* fw  = (const float*)d_in[6];
    const float* fb  = (const float*)d_in[7];
    float* out = (float*)d_out;

    int nsm = 148;
    cudaDeviceGetAttribute(&nsm, cudaDevAttrMultiProcessorCount, 0);
    if (nsm * 16 < NN / 4) nsm = (NN / 4 + 15) / 16;  // ensure all rows covered

    cudaFuncSetAttribute(k_gemv, cudaFuncAttributeMaxDynamicSharedMemorySize, 131072);

    k_pool<<<(BB * NN) / 64, 128>>>(x, c1w, c1b);
    k_gemv<<<nsm, 512, 131072>>>(fw, fb);
    k_out<<<(BB * NN) / 128, 128>>>(x, g3w, g3b, out);
}

// round 5
// speedup vs baseline: 2.3627x; 1.3122x over previous
#include <cuda_runtime.h>

#define BB 4
#define TT 8
#define CC 64
#define FF 16
#define NN 8192   // T*H*W
#define HW 1024

typedef unsigned long long u64;

// Scratch: pooled transposed as float4 over batch, and sigmoid output v.
__device__ float4 g_p4[NN];        // g_p4[n] = (pooled[b=0..3][n])
__device__ float  g_v[BB * NN];    // v[b*N + n]

__device__ __forceinline__ u64 pack2(unsigned int w) {
    u64 r;
    asm("mov.b64 %0, {%1, %1};" : "=l"(r) : "r"(w));
    return r;
}
__device__ __forceinline__ void fma2(u64& acc, u64 a, u64 b) {
    asm("fma.rn.f32x2 %0, %1, %2, %0;" : "+l"(acc) : "l"(a), "l"(b));
}
__device__ __forceinline__ void unpack2(u64 v, float& lo, float& hi) {
    unsigned int l, h;
    asm("mov.b64 {%0, %1}, %2;" : "=r"(l), "=r"(h) : "l"(v));
    lo = __uint_as_float(l);
    hi = __uint_as_float(h);
}

// ---------------------------------------------------------------------------
// Kernel 1: pooled[b,n] = sum_c mean_f(conv1_w[f,c]) * x[b,t,c,hw] + mean_f(b)
// Each group of 4 lanes handles one (b, n0..n0+3) output quad: float4 over hw,
// c split 4 ways (16 c each), warp-shuffle combine. 256 blocks x 128 threads,
// 16 independent float4 loads per thread.
// ---------------------------------------------------------------------------
__global__ __launch_bounds__(128) void k_pool(const float* __restrict__ x,
                                              const float* __restrict__ c1w,
                                              const float* __restrict__ c1b) {
    __shared__ float swb[CC];
    __shared__ float sbb;
    int tid = threadIdx.x;
    if (tid < CC) {
        float s = 0.f;
        #pragma unroll
        for (int f = 0; f < FF; f++) s += c1w[f * CC + tid];
        swb[tid] = s * (1.0f / FF);
    }
    if (tid == 0) {
        float s = 0.f;
        #pragma unroll
        for (int f = 0; f < FF; f++) s += c1b[f];
        sbb = s * (1.0f / FF);
    }
    __syncthreads();

    int q = tid >> 2;                 // output quad within block (0..31)
    int s = tid & 3;                  // c-split (0..3)
    int G = blockIdx.x * 32 + q;      // global quad id, 0..8191
    int b  = G >> 11;
    int nq = G & 2047;
    int n0 = nq * 4;
    int t  = n0 >> 10;
    int hw4 = (n0 & (HW - 1)) >> 2;

    const float4* xp = (const float4*)x
        + ((size_t)((b * TT + t) * CC + s * 16)) * (HW / 4) + hw4;

    float4 a = make_float4(0.f, 0.f, 0.f, 0.f);
    #pragma unroll
    for (int c = 0; c < 16; c++) {
        float w = swb[s * 16 + c];
        float4 xv = xp[c * (HW / 4)];
        a.x += w * xv.x; a.y += w * xv.y; a.z += w * xv.z; a.w += w * xv.w;
    }
    // combine the 4 c-splits (adjacent lanes)
    #pragma unroll
    for (int off = 1; off < 4; off <<= 1) {
        a.x += __shfl_xor_sync(0xffffffffu, a.x, off);
        a.y += __shfl_xor_sync(0xffffffffu, a.y, off);
        a.z += __shfl_xor_sync(0xffffffffu, a.z, off);
        a.w += __shfl_xor_sync(0xffffffffu, a.w, off);
    }
    if (s == 0) {
        float bb = sbb;
        float* gp = (float*)g_p4;
        gp[(n0 + 0) * 4 + b] = a.x + bb;
        gp[(n0 + 1) * 4 + b] = a.y + bb;
        gp[(n0 + 2) * 4 + b] = a.z + bb;
        gp[(n0 + 3) * 4 + b] = a.w + bb;
    }
}

// ---------------------------------------------------------------------------
// Kernel 2: v[b,n] = sigmoid( sum_m pooled[b,m] * W[n,m] + bias[n] )
// grid = 128 CTAs exactly (2048 warp-tasks / 16 warps), 512 threads, 128KB
// smem (pooled as 4 deinterleaved float4 planes -> conflict-free LDS.128).
// Warp gw handles rows 4gw..4gw+3 for all 4 batches. Packed f32x2 FMA
// (FFMA2) halves FMA-pipe pressure and register pressure so the 4 streaming
// LDG.128/trip (x2 unroll = 8 in flight) overlap the math. DRAM-bound.
// ---------------------------------------------------------------------------
__global__ __launch_bounds__(512) void k_gemv(const float* __restrict__ Wm,
                                              const float* __restrict__ bias) {
    extern __shared__ float4 sp[];   // sp[j*2048 + i] = g_p4[4*i + j], 128KB
    for (int idx = threadIdx.x; idx < NN; idx += 512)
        sp[(idx & 3) * 2048 + (idx >> 2)] = g_p4[idx];
    __syncthreads();

    int lane = threadIdx.x & 31;
    int gw   = blockIdx.x * 16 + (threadIdx.x >> 5);   // 0..2047, exact
    int n0 = gw * 4;
    const float4* w0 = (const float4*)Wm + (size_t)n0 * (NN / 4);
    const ulonglong2* spu = (const ulonglong2*)sp;     // .x=(b0,b1) .y=(b2,b3)

    u64 aL[4], aH[4];                // [row r]: L = batches 0,1; H = batches 2,3
    #pragma unroll
    for (int r = 0; r < 4; r++) { aL[r] = 0ull; aH[r] = 0ull; }

    #pragma unroll 2
    for (int i = lane; i < NN / 4; i += 32) {
        float4 wv0 = __ldcs(w0 + i);
        float4 wv1 = __ldcs(w0 + 2048 + i);
        float4 wv2 = __ldcs(w0 + 4096 + i);
        float4 wv3 = __ldcs(w0 + 6144 + i);
        ulonglong2 p0 = spu[i];
        ulonglong2 p1 = spu[2048 + i];
        ulonglong2 p2 = spu[4096 + i];
        ulonglong2 p3 = spu[6144 + i];
        float4 wv[4] = {wv0, wv1, wv2, wv3};
        #pragma unroll
        for (int r = 0; r < 4; r++) {
            u64 wx = pack2(__float_as_uint(wv[r].x));
            fma2(aL[r], wx, p0.x); fma2(aH[r], wx, p0.y);
            u64 wy = pack2(__float_as_uint(wv[r].y));
            fma2(aL[r], wy, p1.x); fma2(aH[r], wy, p1.y);
            u64 wz = pack2(__float_as_uint(wv[r].z));
            fma2(aL[r], wz, p2.x); fma2(aH[r], wz, p2.y);
            u64 ww = pack2(__float_as_uint(wv[r].w));
            fma2(aL[r], ww, p3.x); fma2(aH[r], ww, p3.y);
        }
    }

    float acc[16];
    #pragma unroll
    for (int r = 0; r < 4; r++) {
        unpack2(aL[r], acc[r * 4 + 0], acc[r * 4 + 1]);
        unpack2(aH[r], acc[r * 4 + 2], acc[r * 4 + 3]);
    }
    #pragma unroll
    for (int k = 0; k < 16; k++)
        #pragma unroll
        for (int off = 16; off > 0; off >>= 1)
            acc[k] += __shfl_xor_sync(0xffffffffu, acc[k], off);

    if (lane < 16) {
        int r = lane >> 2, b = lane & 3;
        float z = acc[lane] + bias[n0 + r];
        g_v[b * NN + n0 + r] = 1.0f / (1.0f + __expf(-z));
    }
}

// ---------------------------------------------------------------------------
// Kernel 3: out[b,t,f,h,w] = v[b,n] * (sum_c g3_w[f,c]*x[b,t,c,hw] + g3_b[f])
// 256 blocks x 128 threads, 16 f-accumulators, weights in SMEM.
// ---------------------------------------------------------------------------
__global__ __launch_bounds__(128) void k_out(const float* __restrict__ x,
                                             const float* __restrict__ g3w,
                                             const float* __restrict__ g3b,
                                             float* __restrict__ out) {
    __shared__ float sw[FF * CC];
    __shared__ float sb[FF];
    for (int idx = threadIdx.x; idx < FF * CC; idx += 128) sw[idx] = g3w[idx];
    if (threadIdx.x < FF) sb[threadIdx.x] = g3b[threadIdx.x];
    __syncthreads();

    int g  = blockIdx.x * 128 + threadIdx.x;
    int b  = g >> 13;
    int n  = g & (NN - 1);
    int t  = n >> 10;
    int hw = n & (HW - 1);
    const float* xp = x + (size_t)((b * TT + t) * CC) * HW + hw;

    float acc[FF];
    #pragma unroll
    for (int f = 0; f < FF; f++) acc[f] = sb[f];

    #pragma unroll 8
    for (int c = 0; c < CC; c++) {
        float xv = xp[c * HW];
        #pragma unroll
        for (int f = 0; f < FF; f++) acc[f] += sw[f * CC + c] * xv;
    }

    float v = g_v[b * NN + n];
    float* op = out + (size_t)((b * TT + t) * FF) * HW + hw;
    #pragma unroll
    for (int f = 0; f < FF; f++) op[f * HW] = v * acc[f];
}

extern "C" void kernel_launch(void* const* d_in, const int* in_sizes, int n_in,
                              void* d_out, int out_size) {
    const float* x   = (const float*)d_in[0];
    // d_in[1] = x1, unused by the reference forward
    const float* c1w = (const float*)d_in[2];
    const float* c1b = (const float*)d_in[3];
    const float* g3w = (const float*)d_in[4];
    const float* g3b = (const float*)d_in[5];
    const float* fw  = (const float*)d_in[6];
    const float* fb  = (const float*)d_in[7];
    float* out = (float*)d_out;

    cudaFuncSetAttribute(k_gemv, cudaFuncAttributeMaxDynamicSharedMemorySize, 131072);

    k_pool<<<256, 128>>>(x, c1w, c1b);
    k_gemv<<<128, 512, 131072>>>(fw, fb);          // 128*16 warps = 2048 tasks, exact
    k_out<<<(BB * NN) / 128, 128>>>(x, g3w, g3b, out);
}

// round 9
// speedup vs baseline: 2.5132x; 1.0637x over previous
#include <cuda_runtime.h>

#define BB 4
#define TT 8
#define CC 64
#define FF 16
#define NN 8192   // T*H*W
#define HW 1024

typedef unsigned long long u64;

// Scratch: pooled transposed as float4 over batch, and sigmoid output v.
__device__ float4 g_p4[NN];        // g_p4[n] = (pooled[b=0..3][n])
__device__ float  g_v[BB * NN];    // v[b*N + n]

__device__ __forceinline__ u64 pack2(unsigned int w) {
    u64 r;
    asm("mov.b64 %0, {%1, %1};" : "=l"(r) : "r"(w));
    return r;
}
__device__ __forceinline__ void fma2(u64& acc, u64 a, u64 b) {
    asm("fma.rn.f32x2 %0, %1, %2, %0;" : "+l"(acc) : "l"(a), "l"(b));
}
__device__ __forceinline__ void unpack2(u64 v, float& lo, float& hi) {
    unsigned int l, h;
    asm("mov.b64 {%0, %1}, %2;" : "=r"(l), "=r"(h) : "l"(v));
    lo = __uint_as_float(l);
    hi = __uint_as_float(h);
}

// ---------------------------------------------------------------------------
// Kernel 1: pooled[b,n] = sum_c mean_f(conv1_w[f,c]) * x[b,t,c,hw] + mean_f(b)
// 16-way c-split: group of 16 lanes handles one (b, n0..n0+3) quad; each lane
// does 4 independent float4 loads (low reg pressure, MLP via 131K threads),
// then a 4-round shuffle tree combines the splits. 1024 blocks x 128 threads.
// ---------------------------------------------------------------------------
__global__ __launch_bounds__(128) void k_pool(const float* __restrict__ x,
                                              const float* __restrict__ c1w,
                                              const float* __restrict__ c1b) {
    __shared__ float swb[CC];
    __shared__ float sbb;
    int tid = threadIdx.x;
    if (tid < CC) {
        float s = 0.f;
        #pragma unroll
        for (int f = 0; f < FF; f++) s += c1w[f * CC + tid];
        swb[tid] = s * (1.0f / FF);
    }
    if (tid == 0) {
        float s = 0.f;
        #pragma unroll
        for (int f = 0; f < FF; f++) s += c1b[f];
        sbb = s * (1.0f / FF);
    }
    __syncthreads();

    int s  = tid & 15;                // c-split (0..15), 4 channels each
    int q  = tid >> 4;                // quad within block (0..7)
    int G  = blockIdx.x * 8 + q;      // global quad id, 0..8191
    int b  = G >> 11;
    int nq = G & 2047;
    int n0 = nq * 4;
    int t  = n0 >> 10;
    int hw4 = (n0 & (HW - 1)) >> 2;

    const float4* xp = (const float4*)x
        + ((size_t)((b * TT + t) * CC + s * 4)) * (HW / 4) + hw4;

    // 4 independent loads, explicitly named so they batch.
    float4 x0 = xp[0];
    float4 x1 = xp[HW / 4];
    float4 x2 = xp[2 * (HW / 4)];
    float4 x3 = xp[3 * (HW / 4)];
    float w0v = swb[s * 4 + 0], w1v = swb[s * 4 + 1];
    float w2v = swb[s * 4 + 2], w3v = swb[s * 4 + 3];

    float4 a;
    a.x = w0v * x0.x + w1v * x1.x + w2v * x2.x + w3v * x3.x;
    a.y = w0v * x0.y + w1v * x1.y + w2v * x2.y + w3v * x3.y;
    a.z = w0v * x0.z + w1v * x1.z + w2v * x2.z + w3v * x3.z;
    a.w = w0v * x0.w + w1v * x1.w + w2v * x2.w + w3v * x3.w;

    #pragma unroll
    for (int off = 1; off < 16; off <<= 1) {
        a.x += __shfl_xor_sync(0xffffffffu, a.x, off);
        a.y += __shfl_xor_sync(0xffffffffu, a.y, off);
        a.z += __shfl_xor_sync(0xffffffffu, a.z, off);
        a.w += __shfl_xor_sync(0xffffffffu, a.w, off);
    }
    if (s == 0) {
        float bb = sbb;
        float* gp = (float*)g_p4;
        gp[(n0 + 0) * 4 + b] = a.x + bb;
        gp[(n0 + 1) * 4 + b] = a.y + bb;
        gp[(n0 + 2) * 4 + b] = a.z + bb;
        gp[(n0 + 3) * 4 + b] = a.w + bb;
    }
}

// ---------------------------------------------------------------------------
// Kernel 2: v[b,n] = sigmoid( sum_m pooled[b,m] * W[n,m] + bias[n] )
// 128 CTAs x 512 threads (16 warps), 128KB smem (pooled in 4 deinterleaved
// float4 planes -> conflict-free LDS.128). Warp gw owns rows 4gw..4gw+3 for
// all 4 batches, packed f32x2 accumulation. EXPLICIT 2-stage software
// pipeline: each stage's 4 LDG.128 are issued a full COMPUTE stage before
// their FMA chain consumes them -> 8 LDG.128 (4KB) per warp truly in flight,
// 64KB/SM >> the ~10KB bandwidth-latency product. DRAM-bound by design.
// ---------------------------------------------------------------------------
__global__ __launch_bounds__(512) void k_gemv(const float* __restrict__ Wm,
                                              const float* __restrict__ bias) {
    extern __shared__ float4 sp[];   // sp[j*2048 + i] = g_p4[4*i + j], 128KB
    for (int idx = threadIdx.x; idx < NN; idx += 512)
        sp[(idx & 3) * 2048 + (idx >> 2)] = g_p4[idx];
    __syncthreads();

    int lane = threadIdx.x & 31;
    int gw   = blockIdx.x * 16 + (threadIdx.x >> 5);   // 0..2047, exact
    int n0 = gw * 4;
    const float4* w0 = (const float4*)Wm + (size_t)n0 * (NN / 4);
    const ulonglong2* spu = (const ulonglong2*)sp;     // .x=(b0,b1) .y=(b2,b3)

    u64 aL[4], aH[4];                // [row r]: L = batches 0,1; H = batches 2,3
    #pragma unroll
    for (int r = 0; r < 4; r++) { aL[r] = 0ull; aH[r] = 0ull; }

#define LOADST(wv, pv, I)                                                     \
    {                                                                         \
        wv[0] = __ldcs(w0 + (I));                                             \
        wv[1] = __ldcs(w0 + 2048 + (I));                                      \
        wv[2] = __ldcs(w0 + 4096 + (I));                                      \
        wv[3] = __ldcs(w0 + 6144 + (I));                                      \
        pv[0] = spu[(I)];                                                     \
        pv[1] = spu[2048 + (I)];                                              \
        pv[2] = spu[4096 + (I)];                                              \
        pv[3] = spu[6144 + (I)];                                              \
    }

#define COMPUTE(wv, pv)                                                       \
    {                                                                         \
        _Pragma("unroll")                                                     \
        for (int r = 0; r < 4; r++) {                                         \
            u64 wx = pack2(__float_as_uint(wv[r].x));                         \
            fma2(aL[r], wx, pv[0].x); fma2(aH[r], wx, pv[0].y);               \
            u64 wy = pack2(__float_as_uint(wv[r].y));                         \
            fma2(aL[r], wy, pv[1].x); fma2(aH[r], wy, pv[1].y);               \
            u64 wz = pack2(__float_as_uint(wv[r].z));                         \
            fma2(aL[r], wz, pv[2].x); fma2(aH[r], wz, pv[2].y);               \
            u64 ww = pack2(__float_as_uint(wv[r].w));                         \
            fma2(aL[r], ww, pv[3].x); fma2(aH[r], ww, pv[3].y);               \
        }                                                                     \
    }

    float4 wA[4], wB[4];
    ulonglong2 pA[4], pB[4];
    LOADST(wA, pA, lane);
    LOADST(wB, pB, lane + 32);

    // NN/4 = 2048 = 64 * 32 trips total; pipeline depth 2 stages of 32.
    for (int i = lane + 64; i < NN / 4; i += 64) {
        COMPUTE(wA, pA);
        LOADST(wA, pA, i);            // consumed one full stage later
        COMPUTE(wB, pB);
        LOADST(wB, pB, i + 32);
    }
    COMPUTE(wA, pA);
    COMPUTE(wB, pB);
#undef LOADST
#undef COMPUTE

    float acc[16];
    #pragma unroll
    for (int r = 0; r < 4; r++) {
        unpack2(aL[r], acc[r * 4 + 0], acc[r * 4 + 1]);
        unpack2(aH[r], acc[r * 4 + 2], acc[r * 4 + 3]);
    }
    #pragma unroll
    for (int k = 0; k < 16; k++)
        #pragma unroll
        for (int off = 16; off > 0; off >>= 1)
            acc[k] += __shfl_xor_sync(0xffffffffu, acc[k], off);

    if (lane < 16) {
        int r = lane >> 2, b = lane & 3;
        float z = acc[lane] + bias[n0 + r];
        g_v[b * NN + n0 + r] = 1.0f / (1.0f + __expf(-z));
    }
}

// ---------------------------------------------------------------------------
// Kernel 3: out[b,t,f,h,w] = v[b,n] * (sum_c g3_w[f,c]*x[b,t,c,hw] + g3_b[f])
// 256 blocks x 128 threads, 16 f-accumulators, weights in SMEM.
// ---------------------------------------------------------------------------
__global__ __launch_bounds__(128) void k_out(const float* __restrict__ x,
                                             const float* __restrict__ g3w,
                                             const float* __restrict__ g3b,
                                             float* __restrict__ out) {
    __shared__ float sw[FF * CC];
    __shared__ float sb[FF];
    for (int idx = threadIdx.x; idx < FF * CC; idx += 128) sw[idx] = g3w[idx];
    if (threadIdx.x < FF) sb[threadIdx.x] = g3b[threadIdx.x];
    __syncthreads();

    int g  = blockIdx.x * 128 + threadIdx.x;
    int b  = g >> 13;
    int n  = g & (NN - 1);
    int t  = n >> 10;
    int hw = n & (HW - 1);
    const float* xp = x + (size_t)((b * TT + t) * CC) * HW + hw;

    float acc[FF];
    #pragma unroll
    for (int f = 0; f < FF; f++) acc[f] = sb[f];

    #pragma unroll 8
    for (int c = 0; c < CC; c++) {
        float xv = xp[c * HW];
        #pragma unroll
        for (int f = 0; f < FF; f++) acc[f] += sw[f * CC + c] * xv;
    }

    float v = g_v[b * NN + n];
    float* op = out + (size_t)((b * TT + t) * FF) * HW + hw;
    #pragma unroll
    for (int f = 0; f < FF; f++) op[f * HW] = v * acc[f];
}

extern "C" void kernel_launch(void* const* d_in, const int* in_sizes, int n_in,
                              void* d_out, int out_size) {
    const float* x   = (const float*)d_in[0];
    // d_in[1] = x1, unused by the reference forward
    const float* c1w = (const float*)d_in[2];
    const float* c1b = (const float*)d_in[3];
    const float* g3w = (const float*)d_in[4];
    const float* g3b = (const float*)d_in[5];
    const float* fw  = (const float*)d_in[6];
    const float* fb  = (const float*)d_in[7];
    float* out = (float*)d_out;

    cudaFuncSetAttribute(k_gemv, cudaFuncAttributeMaxDynamicSharedMemorySize, 131072);

    k_pool<<<1024, 128>>>(x, c1w, c1b);
    k_gemv<<<128, 512, 131072>>>(fw, fb);          // 128*16 warps = 2048 tasks, exact
    k_out<<<(BB * NN) / 128, 128>>>(x, g3w, g3b, out);
}